// round 13
// baseline (speedup 1.0000x reference)
#include <cuda_runtime.h>
#include <cstdint>

#define NBATCH 4
#define LRES   256
#define NATOM  14
#define FEAT   128
#define MPAIR  196      // NATOM*NATOM
#define MAXAA  22
#define NAPAIR 484      // MAXAA*MAXAA
#define NREL   65
#define TPAIR  64       // pairs per block tile (8 i-rows x 8 j-cols)
#define NTHREADS 256
#define CHUNK  16       // weight chunk rows (sized so 2 CTAs/SM fit in smem)
#define K3     154      // stage-3 K: 128 dist + 26 dihedral (contiguous ow1 rows 256..409)

typedef unsigned long long ull;

// ---------------- scratch (static __device__ — no allocations allowed) ----------------
__device__ float g_softc[NAPAIR * MPAIR];          // softplus(distcoef_embed)
__device__ float g_preA [NAPAIR * FEAT];           // aa_pair_embed @ out_w1[0:128]
__device__ float g_preR [NREL   * FEAT];           // relpos_embed  @ out_w1[128:256]
__device__ float g_dihed[NBATCH * LRES * LRES * 2];// (phi, psi) per pair

// ---------------- packed f32x2 helpers ----------------
__device__ __forceinline__ ull pack2(float lo, float hi) {
    ull r; asm("mov.b64 %0, {%1, %2};" : "=l"(r) : "f"(lo), "f"(hi)); return r;
}
__device__ __forceinline__ void fma2(ull& d, ull a, ull b) {
    asm("fma.rn.f32x2 %0, %1, %2, %0;" : "+l"(d) : "l"(a), "l"(b));
}
__device__ __forceinline__ float2 unpack2(ull v) {
    float2 r; asm("mov.b64 {%0, %1}, %2;" : "=f"(r.x), "=f"(r.y) : "l"(v)); return r;
}

// ---------------- small precompute kernels ----------------
__global__ void softc_kernel(const float* __restrict__ distcoef) {
    int idx = blockIdx.x * 256 + threadIdx.x;
    if (idx < NAPAIR * MPAIR) {
        float x = distcoef[idx];
        g_softc[idx] = (x > 20.f) ? x : log1pf(expf(x));
    }
}

__global__ void pretab_kernel(const float* __restrict__ aa_pair_embed,
                              const float* __restrict__ relpos_embed,
                              const float* __restrict__ ow1) {
    __shared__ float e[FEAT];
    int b = blockIdx.x, f = threadIdx.x;
    if (b < NAPAIR) {
        e[f] = aa_pair_embed[b * FEAT + f];
        __syncthreads();
        float acc = 0.f;
        #pragma unroll 8
        for (int k = 0; k < FEAT; k++) acc += e[k] * ow1[k * FEAT + f];
        g_preA[b * FEAT + f] = acc;
    } else {
        int r = b - NAPAIR;
        e[f] = relpos_embed[r * FEAT + f];
        __syncthreads();
        float acc = 0.f;
        #pragma unroll 8
        for (int k = 0; k < FEAT; k++) acc += e[k] * ow1[(FEAT + k) * FEAT + f];
        g_preR[r * FEAT + f] = acc;
    }
}

__device__ __forceinline__ float3 f3sub(float3 a, float3 b) { return make_float3(a.x-b.x, a.y-b.y, a.z-b.z); }
__device__ __forceinline__ float3 f3cross(float3 a, float3 b) {
    return make_float3(a.y*b.z - a.z*b.y, a.z*b.x - a.x*b.z, a.x*b.y - a.y*b.x);
}
__device__ __forceinline__ float f3dot(float3 a, float3 b) { return a.x*b.x + a.y*b.y + a.z*b.z; }

__device__ __forceinline__ float dihedral_f(float3 p0, float3 p1, float3 p2, float3 p3) {
    float3 v0 = f3sub(p2, p1), v1 = f3sub(p0, p1), v2 = f3sub(p3, p2);
    float3 u1 = f3cross(v0, v1), u2 = f3cross(v0, v2);
    float nn = f3dot(u1, u1) * f3dot(u2, u2);
    if (!(nn > 0.f)) return 0.f;
    float cosv = f3dot(u1, u2) * rsqrtf(nn);
    cosv = fminf(fmaxf(cosv, -0.999999f), 0.999999f);
    float sd = f3dot(f3cross(v1, v2), v0);
    float sgn = (sd > 0.f) ? 1.f : ((sd < 0.f) ? -1.f : 0.f);
    float d = sgn * acosf(cosv);
    return isfinite(d) ? d : 0.f;
}

__global__ void dihed_kernel(const float* __restrict__ pos) {
    int idx = blockIdx.x * 256 + threadIdx.x;        // NB*L*L threads exactly
    int n = idx >> 16, i = (idx >> 8) & 255, j = idx & 255;
    const float* pi = pos + (size_t)(n * LRES + i) * NATOM * 3;
    const float* pj = pos + (size_t)(n * LRES + j) * NATOM * 3;
    float3 Ni  = make_float3(pi[0], pi[1], pi[2]);
    float3 CAi = make_float3(pi[3], pi[4], pi[5]);
    float3 Ci  = make_float3(pi[6], pi[7], pi[8]);
    float3 Nj  = make_float3(pj[0], pj[1], pj[2]);
    float3 CAj = make_float3(pj[3], pj[4], pj[5]);
    float3 Cj  = make_float3(pj[6], pj[7], pj[8]);
    float phi = dihedral_f(Ci, Nj, CAj, Cj);
    float psi = dihedral_f(Ni, CAi, Ci, Nj);
    g_dihed[(size_t)idx * 2 + 0] = phi;
    g_dihed[(size_t)idx * 2 + 1] = psi;
}

// ---------------- fused main kernel ----------------
// Tile: 64 pairs (8 i x 8 j) x 128 feat. 8 warps, 256 threads, 2 CTAs/SM.
// warp -> 16-feature slice [warp*16, warp*16+16). Within the warp:
//   q = lane&3  -> 4-feature sub-slice  f in [fbase+4q, fbase+4q+4)
//   g = lane>>2 -> pair octet           p in [8g, 8g+8)
//   sw = (g>>2)&1 -> act half-swap so each act LDS.128 covers a full 128B
//                    conflict-free line across the warp.
// acc slot jp (0..3) holds pairs (P(jp), P(jp)+1) where
//   P(jp) = 8g + 4*(sw ^ (jp>>1)) + 2*(jp&1).
struct __align__(16) Smem {
    float bufG[MPAIR * TPAIR];  // 50.2KB: stage1 act; rows 0..153 = stage3 act
    float bufB[FEAT * TPAIR];   // 32KB ping-pong
    float sW[2][CHUNK * FEAT];  // 16KB double-buffered weight chunks
    float dcodeK[26 * TPAIR];   // 6.7KB dihedral codes, k-major [t][p]
    float posI[8 * NATOM * 3];
    float posJ[8 * NATOM * 3];
    float maskI[8 * NATOM];
    float maskJ[8 * NATOM];
    float b1[FEAT]; float b2[FEAT]; float b3[FEAT]; float b4[FEAT]; float b5[FEAT];
    float sc[TPAIR]; float mp[TPAIR];
    int aap[TPAIR]; int rel[TPAIR];
    int aaI[8]; int aaJ[8]; int resI[8]; int resJ[8]; int chI[8]; int chJ[8];
};

__device__ __forceinline__ int slot_pair(int g, int sw, int jp) {
    return 8 * g + 4 * (sw ^ (jp >> 1)) + 2 * (jp & 1);
}

// Weight chunks: smem double-buffer, ONE __syncthreads per chunk.
template<int K>
__device__ __forceinline__ void gemm_db(const float* __restrict__ Wg,
                                        const float* __restrict__ sAct,
                                        float (*__restrict__ sW)[CHUNK * FEAT],
                                        ull acc[4][4],
                                        int tid, int lane, int fbase) {
    constexpr int NCH = (K + CHUNK - 1) / CHUNK;
    const int q = lane & 3, g = lane >> 2;
    const int sw = (g >> 2) & 1;
    float4 r0, r1;
    {   // chunk 0: load + commit to buf0 (sW unused since previous gemm's final sync)
        const float4* src = (const float4*)Wg;
        constexpr int lim0 = (K < CHUNK ? K : CHUNK) * 32;
        float4* dst = (float4*)sW[0];
        if (tid < lim0)       { r0 = src[tid];       dst[tid] = r0; }
        if (tid + 256 < lim0) { r1 = src[tid + 256]; dst[tid + 256] = r1; }
    }
    if (NCH > 1) {  // prefetch chunk 1 into regs
        const float4* src = (const float4*)(Wg + CHUNK * FEAT);
        const int lim = ((K - CHUNK < CHUNK) ? (K - CHUNK) : CHUNK) * 32;
        if (tid < lim)       r0 = src[tid];
        if (tid + 256 < lim) r1 = src[tid + 256];
    }
    #pragma unroll 1
    for (int c = 0; c < NCH; c++) {
        __syncthreads();  // chunk c committed & visible; buf[(c+1)&1] free to overwrite
        if (c + 1 < NCH) {  // commit chunk c+1 (regs -> other buffer) during compute window
            const int lim = (((K - (c + 1) * CHUNK) < CHUNK) ? (K - (c + 1) * CHUNK) : CHUNK) * 32;
            float4* dst = (float4*)sW[(c + 1) & 1];
            if (tid < lim)       dst[tid] = r0;
            if (tid + 256 < lim) dst[tid + 256] = r1;
        }
        if (c + 2 < NCH) {  // prefetch chunk c+2
            const float4* src = (const float4*)(Wg + (c + 2) * CHUNK * FEAT);
            const int lim = (((K - (c + 2) * CHUNK) < CHUNK) ? (K - (c + 2) * CHUNK) : CHUNK) * 32;
            if (tid < lim)       r0 = src[tid];
            if (tid + 256 < lim) r1 = src[tid + 256];
        }
        const int k0 = c * CHUNK;
        const int rows = (K - k0 < CHUNK) ? (K - k0) : CHUNK;
        const float* wq     = sW[c & 1] + fbase + 4 * q;
        const float* abase0 = sAct + k0 * TPAIR + 8 * g + 4 * sw;        // slots 0,1
        const float* abase1 = sAct + k0 * TPAIR + 8 * g + 4 * (sw ^ 1);  // slots 2,3
        #pragma unroll 8
        for (int kk = 0; kk < rows; kk++) {
            float4 a0 = *(const float4*)(abase0 + kk * TPAIR);
            float4 a1 = *(const float4*)(abase1 + kk * TPAIR);
            float4 wv = *(const float4*)(wq + kk * FEAT);
            ull au0 = pack2(a0.x, a0.y), au1 = pack2(a0.z, a0.w);
            ull au2 = pack2(a1.x, a1.y), au3 = pack2(a1.z, a1.w);
            ull w0 = pack2(wv.x, wv.x), w1 = pack2(wv.y, wv.y);
            ull w2 = pack2(wv.z, wv.z), w3 = pack2(wv.w, wv.w);
            fma2(acc[0][0], au0, w0); fma2(acc[0][1], au1, w0);
            fma2(acc[0][2], au2, w0); fma2(acc[0][3], au3, w0);
            fma2(acc[1][0], au0, w1); fma2(acc[1][1], au1, w1);
            fma2(acc[1][2], au2, w1); fma2(acc[1][3], au3, w1);
            fma2(acc[2][0], au0, w2); fma2(acc[2][1], au1, w2);
            fma2(acc[2][2], au2, w2); fma2(acc[2][3], au3, w2);
            fma2(acc[3][0], au0, w3); fma2(acc[3][1], au1, w3);
            fma2(acc[3][2], au2, w3); fma2(acc[3][3], au3, w3);
        }
    }
    __syncthreads();  // protect act buffers + sW before next stage
}

// relu(acc + bias) -> dst in k-major layout dst[f][p]
// Slot order staggered by q so the 4 q-lanes hit distinct bank slices.
__device__ __forceinline__ void epilogue(ull acc[4][4],
                                         const float* __restrict__ bias,
                                         float* __restrict__ dst, int lane, int fbase) {
    const int q = lane & 3, g = lane >> 2;
    const int sw = (g >> 2) & 1;
    #pragma unroll
    for (int fi = 0; fi < 4; fi++) {
        int f = fbase + 4 * q + fi;
        float bf = bias[f];
        #pragma unroll
        for (int t = 0; t < 4; t++) {
            int jp = (t + q) & 3;
            int p = slot_pair(g, sw, jp);
            float2 v = unpack2(acc[fi][jp]);
            float2 o = make_float2(fmaxf(v.x + bf, 0.f), fmaxf(v.y + bf, 0.f));
            *(float2*)&dst[f * TPAIR + p] = o;
        }
    }
}

__device__ __forceinline__ void zero_acc(ull acc[4][4]) {
    #pragma unroll
    for (int a = 0; a < 4; a++)
        #pragma unroll
        for (int b = 0; b < 4; b++) acc[a][b] = 0ull;
}

__global__ void __launch_bounds__(NTHREADS, 2)
fused_kernel(const int* __restrict__ aa, const int* __restrict__ res_nb,
             const int* __restrict__ chain_nb, const float* __restrict__ pos,
             const float* __restrict__ mask,
             const float* __restrict__ dw1, const float* __restrict__ db1,
             const float* __restrict__ dw2, const float* __restrict__ db2,
             const float* __restrict__ ow1, const float* __restrict__ ob1,
             const float* __restrict__ ow2, const float* __restrict__ ob2,
             const float* __restrict__ ow3, const float* __restrict__ ob3,
             float* __restrict__ outp) {
    extern __shared__ char smem_raw[];
    Smem& s = *reinterpret_cast<Smem*>(smem_raw);
    const int tid = threadIdx.x;
    const int warp = tid >> 5, lane = tid & 31;
    const int fbase = warp * 16;
    const int q = lane & 3, g = lane >> 2;
    const int sw = (g >> 2) & 1;
    const int bid = blockIdx.x;
    const int n  = bid >> 10;                // 32*32 tiles per batch
    const int i0 = ((bid >> 5) & 31) * 8;
    const int j0 = (bid & 31) * 8;

    // ---- phase 0: cooperative loads ----
    {
        const float* pbI = pos + (size_t)(n * LRES + i0) * NATOM * 3;
        const float* pbJ = pos + (size_t)(n * LRES + j0) * NATOM * 3;
        for (int idx = tid; idx < 8 * NATOM * 3; idx += NTHREADS) { s.posI[idx] = pbI[idx]; s.posJ[idx] = pbJ[idx]; }
        const float* mbI = mask + (size_t)(n * LRES + i0) * NATOM;
        const float* mbJ = mask + (size_t)(n * LRES + j0) * NATOM;
        if (tid < 8 * NATOM) { s.maskI[tid] = mbI[tid]; s.maskJ[tid] = mbJ[tid]; }
        if (tid < 8) {
            s.aaI[tid]  = aa[n * LRES + i0 + tid];
            s.resI[tid] = res_nb[n * LRES + i0 + tid];
            s.chI[tid]  = chain_nb[n * LRES + i0 + tid];
        }
        if (tid >= 32 && tid < 40) {
            int t = tid - 32;
            s.aaJ[t]  = aa[n * LRES + j0 + t];
            s.resJ[t] = res_nb[n * LRES + j0 + t];
            s.chJ[t]  = chain_nb[n * LRES + j0 + t];
        }
        if (tid >= 64 && tid < 192) {
            int t = tid - 64;
            s.b1[t] = db1[t]; s.b2[t] = db2[t]; s.b3[t] = ob1[t];
            s.b4[t] = ob2[t]; s.b5[t] = ob3[t];
        }
    }
    __syncthreads();

    // ---- phase 0b: per-pair meta + dihedral angular codes (k-major) ----
    if (tid < TPAIR) {
        int ii = tid >> 3, jj = tid & 7;
        s.aap[tid] = s.aaI[ii] * MAXAA + s.aaJ[jj];
        int r = s.resI[ii] - s.resJ[jj];
        s.rel[tid] = min(max(r, -32), 32) + 32;
        s.sc[tid] = (s.chI[ii] == s.chJ[jj]) ? 1.f : 0.f;
        s.mp[tid] = s.maskI[ii * NATOM + 1] * s.maskJ[jj * NATOM + 1];   // CA masks
        const float* dh = &g_dihed[((size_t)(n * LRES + i0 + ii) * LRES + (j0 + jj)) * 2];
        float phi = dh[0], psi = dh[1];
        const float FRQ[6] = {1.f, 2.f, 3.f, 1.f, 0.5f, 1.f / 3.f};
        s.dcodeK[0 * TPAIR + tid]  = phi;
        s.dcodeK[13 * TPAIR + tid] = psi;
        #pragma unroll
        for (int t = 0; t < 6; t++) {
            float sv, cv;
            sincosf(phi * FRQ[t], &sv, &cv);
            s.dcodeK[(1 + t) * TPAIR + tid]  = sv;
            s.dcodeK[(7 + t) * TPAIR + tid]  = cv;
            sincosf(psi * FRQ[t], &sv, &cv);
            s.dcodeK[(14 + t) * TPAIR + tid] = sv;
            s.dcodeK[(20 + t) * TPAIR + tid] = cv;
        }
    }
    __syncthreads();

    // ---- phase 1: masked gaussian distance features, k-major G[m][p] ----
    for (int idx = tid; idx < TPAIR * MPAIR; idx += NTHREADS) {
        int m = idx >> 6;
        int pp = idx & (TPAIR - 1);
        int a = m / NATOM;
        int b = m - a * NATOM;
        int ii = pp >> 3, jj = pp & 7;
        float dx = s.posI[ii * 42 + a * 3 + 0] - s.posJ[jj * 42 + b * 3 + 0];
        float dy = s.posI[ii * 42 + a * 3 + 1] - s.posJ[jj * 42 + b * 3 + 1];
        float dz = s.posI[ii * 42 + a * 3 + 2] - s.posJ[jj * 42 + b * 3 + 2];
        float ss = dx * dx + dy * dy + dz * dz;        // (10*d)^2
        float cc = g_softc[s.aap[pp] * MPAIR + m];
        float gv = __expf(-cc * ss * 0.01f) * (s.maskI[ii * NATOM + a] * s.maskJ[jj * NATOM + b]);
        s.bufG[idx] = gv;
    }
    // gemm's first __syncthreads covers bufG visibility

    ull acc[4][4];

    // ---- stage 1: h1 = relu(G @ dist_w1 + b1) -> bufB ----
    zero_acc(acc);
    gemm_db<MPAIR>(dw1, s.bufG, s.sW, acc, tid, lane, fbase);
    epilogue(acc, s.b1, s.bufB, lane, fbase);

    // ---- stage 2: fd = relu(h1 @ dist_w2 + b2) -> bufG rows 0..127 ----
    zero_acc(acc);
    gemm_db<FEAT>(dw2, s.bufB, s.sW, acc, tid, lane, fbase);
    epilogue(acc, s.b2, s.bufG, lane, fbase);
    // append dihedral codes as act rows 128..153 (visible by stage-3 gemm's first sync)
    for (int idx = tid; idx < 26 * TPAIR; idx += NTHREADS)
        s.bufG[FEAT * TPAIR + idx] = s.dcodeK[idx];

    // ---- stage 3: h = relu(preA + sc*preR + [fd;dihed] @ ow1[256:410] + ob1) -> bufB ----
    #pragma unroll
    for (int jp = 0; jp < 4; jp++) {
        int p0 = slot_pair(g, sw, jp), p1 = p0 + 1;
        float sc0 = s.sc[p0], sc1 = s.sc[p1];
        float4 A0 = *(const float4*)&g_preA[s.aap[p0] * FEAT + fbase + 4 * q];
        float4 R0 = *(const float4*)&g_preR[s.rel[p0] * FEAT + fbase + 4 * q];
        float4 A1 = *(const float4*)&g_preA[s.aap[p1] * FEAT + fbase + 4 * q];
        float4 R1 = *(const float4*)&g_preR[s.rel[p1] * FEAT + fbase + 4 * q];
        acc[0][jp] = pack2(A0.x + sc0 * R0.x, A1.x + sc1 * R1.x);
        acc[1][jp] = pack2(A0.y + sc0 * R0.y, A1.y + sc1 * R1.y);
        acc[2][jp] = pack2(A0.z + sc0 * R0.z, A1.z + sc1 * R1.z);
        acc[3][jp] = pack2(A0.w + sc0 * R0.w, A1.w + sc1 * R1.w);
    }
    gemm_db<K3>(ow1 + 256 * FEAT, s.bufG, s.sW, acc, tid, lane, fbase);
    epilogue(acc, s.b3, s.bufB, lane, fbase);

    // ---- stage 4: h = relu(h @ out_w2 + ob2) -> bufG ----
    zero_acc(acc);
    gemm_db<FEAT>(ow2, s.bufB, s.sW, acc, tid, lane, fbase);
    epilogue(acc, s.b4, s.bufG, lane, fbase);

    // ---- stage 5: out = (h @ out_w3 + ob3) * mask_pair -> global ----
    zero_acc(acc);
    gemm_db<FEAT>(ow3, s.bufG, s.sW, acc, tid, lane, fbase);
    {
        int fofs = fbase + 4 * q;
        float b0 = s.b5[fofs], b1v = s.b5[fofs + 1], b2v = s.b5[fofs + 2], b3v = s.b5[fofs + 3];
        #pragma unroll
        for (int jp = 0; jp < 4; jp++) {
            float2 v0 = unpack2(acc[0][jp]);
            float2 v1 = unpack2(acc[1][jp]);
            float2 v2 = unpack2(acc[2][jp]);
            float2 v3 = unpack2(acc[3][jp]);
            int p0 = slot_pair(g, sw, jp);
            int jj0 = p0 & 7;                  // ii == g always (p0 in [8g, 8g+8))
            float mp0 = s.mp[p0], mp1 = s.mp[p0 + 1];
            float* orow = outp + ((((size_t)n * LRES + (i0 + g)) * LRES + (j0 + jj0)) * FEAT + fofs);
            float4 o0 = make_float4((v0.x + b0) * mp0, (v1.x + b1v) * mp0,
                                    (v2.x + b2v) * mp0, (v3.x + b3v) * mp0);
            float4 o1 = make_float4((v0.y + b0) * mp1, (v1.y + b1v) * mp1,
                                    (v2.y + b2v) * mp1, (v3.y + b3v) * mp1);
            *(float4*)&orow[0]    = o0;
            *(float4*)&orow[FEAT] = o1;
        }
    }
}

// ---------------- launch ----------------
extern "C" void kernel_launch(void* const* d_in, const int* in_sizes, int n_in,
                              void* d_out, int out_size) {
    const int*   aa        = (const int*)  d_in[0];
    const int*   res_nb    = (const int*)  d_in[1];
    const int*   chain_nb  = (const int*)  d_in[2];
    const float* pos       = (const float*)d_in[3];
    const float* mask      = (const float*)d_in[4];
    const float* aap_embed = (const float*)d_in[5];
    const float* rel_embed = (const float*)d_in[6];
    const float* distcoef  = (const float*)d_in[7];
    const float* dw1 = (const float*)d_in[8];
    const float* db1 = (const float*)d_in[9];
    const float* dw2 = (const float*)d_in[10];
    const float* db2 = (const float*)d_in[11];
    const float* ow1 = (const float*)d_in[12];
    const float* ob1 = (const float*)d_in[13];
    const float* ow2 = (const float*)d_in[14];
    const float* ob2 = (const float*)d_in[15];
    const float* ow3 = (const float*)d_in[16];
    const float* ob3 = (const float*)d_in[17];
    float* outp = (float*)d_out;

    cudaFuncSetAttribute(fused_kernel, cudaFuncAttributeMaxDynamicSharedMemorySize,
                         (int)sizeof(Smem));

    softc_kernel<<<(NAPAIR * MPAIR + 255) / 256, 256>>>(distcoef);
    pretab_kernel<<<NAPAIR + NREL, 128>>>(aap_embed, rel_embed, ow1);
    dihed_kernel<<<(NBATCH * LRES * LRES) / 256, 256>>>(pos);
    fused_kernel<<<NBATCH * 32 * 32, NTHREADS, sizeof(Smem)>>>(
        aa, res_nb, chain_nb, pos, mask,
        dw1, db1, dw2, db2, ow1, ob1, ow2, ob2, ow3, ob3, outp);
}

// round 14
// speedup vs baseline: 1.0621x; 1.0621x over previous
#include <cuda_runtime.h>
#include <cstdint>

#define NBATCH 4
#define LRES   256
#define NATOM  14
#define FEAT   128
#define MPAIR  196      // NATOM*NATOM
#define MAXAA  22
#define NAPAIR 484      // MAXAA*MAXAA
#define NREL   65
#define TPAIR  64       // pairs per block tile (8 i-rows x 8 j-cols)
#define NTHREADS 256
#define CHUNK  16       // weight chunk rows (sized so 2 CTAs/SM fit in smem)
#define K3     154      // stage-3 K: 128 dist + 26 dihedral (contiguous ow1 rows 256..409)

typedef unsigned long long ull;

// ---------------- scratch (static __device__ — no allocations allowed) ----------------
__device__ float g_softc[NAPAIR * MPAIR];          // softplus(distcoef_embed)
__device__ float g_preA [NAPAIR * FEAT];           // aa_pair_embed @ out_w1[0:128]
__device__ float g_preR [NREL   * FEAT];           // relpos_embed  @ out_w1[128:256]
__device__ float g_dihed[NBATCH * LRES * LRES * 2];// (phi, psi) per pair

// ---------------- packed f32x2 helpers ----------------
__device__ __forceinline__ ull pack2(float lo, float hi) {
    ull r; asm("mov.b64 %0, {%1, %2};" : "=l"(r) : "f"(lo), "f"(hi)); return r;
}
__device__ __forceinline__ void fma2(ull& d, ull a, ull b) {
    asm("fma.rn.f32x2 %0, %1, %2, %0;" : "+l"(d) : "l"(a), "l"(b));
}
__device__ __forceinline__ float2 unpack2(ull v) {
    float2 r; asm("mov.b64 {%0, %1}, %2;" : "=f"(r.x), "=f"(r.y) : "l"(v)); return r;
}

// ---------------- small precompute kernels ----------------
__global__ void softc_kernel(const float* __restrict__ distcoef) {
    int idx = blockIdx.x * 256 + threadIdx.x;
    if (idx < NAPAIR * MPAIR) {
        float x = distcoef[idx];
        g_softc[idx] = (x > 20.f) ? x : log1pf(expf(x));
    }
}

__global__ void pretab_kernel(const float* __restrict__ aa_pair_embed,
                              const float* __restrict__ relpos_embed,
                              const float* __restrict__ ow1) {
    __shared__ float e[FEAT];
    int b = blockIdx.x, f = threadIdx.x;
    if (b < NAPAIR) {
        e[f] = aa_pair_embed[b * FEAT + f];
        __syncthreads();
        float acc = 0.f;
        #pragma unroll 8
        for (int k = 0; k < FEAT; k++) acc += e[k] * ow1[k * FEAT + f];
        g_preA[b * FEAT + f] = acc;
    } else {
        int r = b - NAPAIR;
        e[f] = relpos_embed[r * FEAT + f];
        __syncthreads();
        float acc = 0.f;
        #pragma unroll 8
        for (int k = 0; k < FEAT; k++) acc += e[k] * ow1[(FEAT + k) * FEAT + f];
        g_preR[r * FEAT + f] = acc;
    }
}

__device__ __forceinline__ float3 f3sub(float3 a, float3 b) { return make_float3(a.x-b.x, a.y-b.y, a.z-b.z); }
__device__ __forceinline__ float3 f3cross(float3 a, float3 b) {
    return make_float3(a.y*b.z - a.z*b.y, a.z*b.x - a.x*b.z, a.x*b.y - a.y*b.x);
}
__device__ __forceinline__ float f3dot(float3 a, float3 b) { return a.x*b.x + a.y*b.y + a.z*b.z; }

__device__ __forceinline__ float dihedral_f(float3 p0, float3 p1, float3 p2, float3 p3) {
    float3 v0 = f3sub(p2, p1), v1 = f3sub(p0, p1), v2 = f3sub(p3, p2);
    float3 u1 = f3cross(v0, v1), u2 = f3cross(v0, v2);
    float nn = f3dot(u1, u1) * f3dot(u2, u2);
    if (!(nn > 0.f)) return 0.f;
    float cosv = f3dot(u1, u2) * rsqrtf(nn);
    cosv = fminf(fmaxf(cosv, -0.999999f), 0.999999f);
    float sd = f3dot(f3cross(v1, v2), v0);
    float sgn = (sd > 0.f) ? 1.f : ((sd < 0.f) ? -1.f : 0.f);
    float d = sgn * acosf(cosv);
    return isfinite(d) ? d : 0.f;
}

__global__ void dihed_kernel(const float* __restrict__ pos) {
    int idx = blockIdx.x * 256 + threadIdx.x;        // NB*L*L threads exactly
    int n = idx >> 16, i = (idx >> 8) & 255, j = idx & 255;
    const float* pi = pos + (size_t)(n * LRES + i) * NATOM * 3;
    const float* pj = pos + (size_t)(n * LRES + j) * NATOM * 3;
    float3 Ni  = make_float3(pi[0], pi[1], pi[2]);
    float3 CAi = make_float3(pi[3], pi[4], pi[5]);
    float3 Ci  = make_float3(pi[6], pi[7], pi[8]);
    float3 Nj  = make_float3(pj[0], pj[1], pj[2]);
    float3 CAj = make_float3(pj[3], pj[4], pj[5]);
    float3 Cj  = make_float3(pj[6], pj[7], pj[8]);
    float phi = dihedral_f(Ci, Nj, CAj, Cj);
    float psi = dihedral_f(Ni, CAi, Ci, Nj);
    g_dihed[(size_t)idx * 2 + 0] = phi;
    g_dihed[(size_t)idx * 2 + 1] = psi;
}

// ---------------- fused main kernel ----------------
// Tile: 64 pairs (8 i x 8 j) x 128 feat. 8 warps, 256 threads, 2 CTAs/SM.
// warp -> 16-feature slice [warp*16, warp*16+16). Within the warp:
//   q = lane&3  -> 4-feature sub-slice  f in [fbase+4q, fbase+4q+4)
//   g = lane>>2 -> pair octet           p in [8g, 8g+8)
// acc[fi][jp] (ull) = (out[8g+2jp][f], out[8g+2jp+1][f]), f = fbase+4q+fi.
// Act loads are ulonglong2 (LDS.128) -> packed f32x2 operands with NO mov.
struct __align__(16) Smem {
    float bufG[MPAIR * TPAIR];  // 50.2KB: stage1 act; rows 0..153 = stage3 act
    float bufB[FEAT * TPAIR];   // 32KB ping-pong
    float sW[2][CHUNK * FEAT];  // 16KB double-buffered weight chunks
    float dcodeK[26 * TPAIR];   // 6.7KB dihedral codes, k-major [t][p]
    float posI[8 * NATOM * 3];
    float posJ[8 * NATOM * 3];
    float maskI[8 * NATOM];
    float maskJ[8 * NATOM];
    float b1[FEAT]; float b2[FEAT]; float b3[FEAT]; float b4[FEAT]; float b5[FEAT];
    float sc[TPAIR]; float mp[TPAIR];
    int aap[TPAIR]; int rel[TPAIR];
    int aaI[8]; int aaJ[8]; int resI[8]; int resJ[8]; int chI[8]; int chJ[8];
};

// Weight chunks: smem double-buffer, ONE __syncthreads per chunk.
template<int K>
__device__ __forceinline__ void gemm_db(const float* __restrict__ Wg,
                                        const float* __restrict__ sAct,
                                        float (*__restrict__ sW)[CHUNK * FEAT],
                                        ull acc[4][4],
                                        int tid, int lane, int fbase) {
    constexpr int NCH = (K + CHUNK - 1) / CHUNK;
    const int q = lane & 3, g = lane >> 2;
    float4 r0, r1;
    {   // chunk 0: load + commit to buf0 (sW unused since previous gemm's final sync)
        const float4* src = (const float4*)Wg;
        constexpr int lim0 = (K < CHUNK ? K : CHUNK) * 32;
        float4* dst = (float4*)sW[0];
        if (tid < lim0)       { r0 = src[tid];       dst[tid] = r0; }
        if (tid + 256 < lim0) { r1 = src[tid + 256]; dst[tid + 256] = r1; }
    }
    if (NCH > 1) {  // prefetch chunk 1 into regs
        const float4* src = (const float4*)(Wg + CHUNK * FEAT);
        const int lim = ((K - CHUNK < CHUNK) ? (K - CHUNK) : CHUNK) * 32;
        if (tid < lim)       r0 = src[tid];
        if (tid + 256 < lim) r1 = src[tid + 256];
    }
    #pragma unroll 1
    for (int c = 0; c < NCH; c++) {
        __syncthreads();  // chunk c committed & visible; buf[(c+1)&1] free to overwrite
        if (c + 1 < NCH) {  // commit chunk c+1 (regs -> other buffer) during compute window
            const int lim = (((K - (c + 1) * CHUNK) < CHUNK) ? (K - (c + 1) * CHUNK) : CHUNK) * 32;
            float4* dst = (float4*)sW[(c + 1) & 1];
            if (tid < lim)       dst[tid] = r0;
            if (tid + 256 < lim) dst[tid + 256] = r1;
        }
        if (c + 2 < NCH) {  // prefetch chunk c+2
            const float4* src = (const float4*)(Wg + (c + 2) * CHUNK * FEAT);
            const int lim = (((K - (c + 2) * CHUNK) < CHUNK) ? (K - (c + 2) * CHUNK) : CHUNK) * 32;
            if (tid < lim)       r0 = src[tid];
            if (tid + 256 < lim) r1 = src[tid + 256];
        }
        const int k0 = c * CHUNK;
        const int rows = (K - k0 < CHUNK) ? (K - k0) : CHUNK;
        const float* wq    = sW[c & 1] + fbase + 4 * q;
        const float* abase = sAct + k0 * TPAIR + 8 * g;
        #pragma unroll 8
        for (int kk = 0; kk < rows; kk++) {
            ulonglong2 au01 = *(const ulonglong2*)(abase + kk * TPAIR);      // pairs 8g..8g+3
            ulonglong2 au23 = *(const ulonglong2*)(abase + kk * TPAIR + 4);  // pairs 8g+4..8g+7
            float4 wv = *(const float4*)(wq + kk * FEAT);
            ull w0 = pack2(wv.x, wv.x), w1 = pack2(wv.y, wv.y);
            ull w2 = pack2(wv.z, wv.z), w3 = pack2(wv.w, wv.w);
            fma2(acc[0][0], au01.x, w0); fma2(acc[0][1], au01.y, w0);
            fma2(acc[0][2], au23.x, w0); fma2(acc[0][3], au23.y, w0);
            fma2(acc[1][0], au01.x, w1); fma2(acc[1][1], au01.y, w1);
            fma2(acc[1][2], au23.x, w1); fma2(acc[1][3], au23.y, w1);
            fma2(acc[2][0], au01.x, w2); fma2(acc[2][1], au01.y, w2);
            fma2(acc[2][2], au23.x, w2); fma2(acc[2][3], au23.y, w2);
            fma2(acc[3][0], au01.x, w3); fma2(acc[3][1], au01.y, w3);
            fma2(acc[3][2], au23.x, w3); fma2(acc[3][3], au23.y, w3);
        }
    }
    __syncthreads();  // protect act buffers + sW before next stage
}

// relu(acc + bias) -> dst in k-major layout dst[f][p] (16 STS.64, contiguous pairs)
__device__ __forceinline__ void epilogue(ull acc[4][4],
                                         const float* __restrict__ bias,
                                         float* __restrict__ dst, int lane, int fbase) {
    const int q = lane & 3, g = lane >> 2;
    #pragma unroll
    for (int fi = 0; fi < 4; fi++) {
        int f = fbase + 4 * q + fi;
        float bf = bias[f];
        #pragma unroll
        for (int jp = 0; jp < 4; jp++) {
            float2 v = unpack2(acc[fi][jp]);
            float2 o = make_float2(fmaxf(v.x + bf, 0.f), fmaxf(v.y + bf, 0.f));
            *(float2*)&dst[f * TPAIR + 8 * g + 2 * jp] = o;
        }
    }
}

__device__ __forceinline__ void zero_acc(ull acc[4][4]) {
    #pragma unroll
    for (int a = 0; a < 4; a++)
        #pragma unroll
        for (int b = 0; b < 4; b++) acc[a][b] = 0ull;
}

__global__ void __launch_bounds__(NTHREADS, 2)
fused_kernel(const int* __restrict__ aa, const int* __restrict__ res_nb,
             const int* __restrict__ chain_nb, const float* __restrict__ pos,
             const float* __restrict__ mask,
             const float* __restrict__ dw1, const float* __restrict__ db1,
             const float* __restrict__ dw2, const float* __restrict__ db2,
             const float* __restrict__ ow1, const float* __restrict__ ob1,
             const float* __restrict__ ow2, const float* __restrict__ ob2,
             const float* __restrict__ ow3, const float* __restrict__ ob3,
             float* __restrict__ outp) {
    extern __shared__ char smem_raw[];
    Smem& s = *reinterpret_cast<Smem*>(smem_raw);
    const int tid = threadIdx.x;
    const int warp = tid >> 5, lane = tid & 31;
    const int fbase = warp * 16;
    const int q = lane & 3, g = lane >> 2;
    const int bid = blockIdx.x;
    const int n  = bid >> 10;                // 32*32 tiles per batch
    const int i0 = ((bid >> 5) & 31) * 8;
    const int j0 = (bid & 31) * 8;

    // ---- phase 0: cooperative loads ----
    {
        const float* pbI = pos + (size_t)(n * LRES + i0) * NATOM * 3;
        const float* pbJ = pos + (size_t)(n * LRES + j0) * NATOM * 3;
        for (int idx = tid; idx < 8 * NATOM * 3; idx += NTHREADS) { s.posI[idx] = pbI[idx]; s.posJ[idx] = pbJ[idx]; }
        const float* mbI = mask + (size_t)(n * LRES + i0) * NATOM;
        const float* mbJ = mask + (size_t)(n * LRES + j0) * NATOM;
        if (tid < 8 * NATOM) { s.maskI[tid] = mbI[tid]; s.maskJ[tid] = mbJ[tid]; }
        if (tid < 8) {
            s.aaI[tid]  = aa[n * LRES + i0 + tid];
            s.resI[tid] = res_nb[n * LRES + i0 + tid];
            s.chI[tid]  = chain_nb[n * LRES + i0 + tid];
        }
        if (tid >= 32 && tid < 40) {
            int t = tid - 32;
            s.aaJ[t]  = aa[n * LRES + j0 + t];
            s.resJ[t] = res_nb[n * LRES + j0 + t];
            s.chJ[t]  = chain_nb[n * LRES + j0 + t];
        }
        if (tid >= 64 && tid < 192) {
            int t = tid - 64;
            s.b1[t] = db1[t]; s.b2[t] = db2[t]; s.b3[t] = ob1[t];
            s.b4[t] = ob2[t]; s.b5[t] = ob3[t];
        }
    }
    __syncthreads();

    // ---- phase 0b: per-pair meta + dihedral angular codes (k-major) ----
    if (tid < TPAIR) {
        int ii = tid >> 3, jj = tid & 7;
        s.aap[tid] = s.aaI[ii] * MAXAA + s.aaJ[jj];
        int r = s.resI[ii] - s.resJ[jj];
        s.rel[tid] = min(max(r, -32), 32) + 32;
        s.sc[tid] = (s.chI[ii] == s.chJ[jj]) ? 1.f : 0.f;
        s.mp[tid] = s.maskI[ii * NATOM + 1] * s.maskJ[jj * NATOM + 1];   // CA masks
        const float* dh = &g_dihed[((size_t)(n * LRES + i0 + ii) * LRES + (j0 + jj)) * 2];
        float phi = dh[0], psi = dh[1];
        const float FRQ[6] = {1.f, 2.f, 3.f, 1.f, 0.5f, 1.f / 3.f};
        s.dcodeK[0 * TPAIR + tid]  = phi;
        s.dcodeK[13 * TPAIR + tid] = psi;
        #pragma unroll
        for (int t = 0; t < 6; t++) {
            float sv, cv;
            sincosf(phi * FRQ[t], &sv, &cv);
            s.dcodeK[(1 + t) * TPAIR + tid]  = sv;
            s.dcodeK[(7 + t) * TPAIR + tid]  = cv;
            sincosf(psi * FRQ[t], &sv, &cv);
            s.dcodeK[(14 + t) * TPAIR + tid] = sv;
            s.dcodeK[(20 + t) * TPAIR + tid] = cv;
        }
    }
    __syncthreads();

    // ---- phase 1: masked gaussian distance features, k-major G[m][p] ----
    for (int idx = tid; idx < TPAIR * MPAIR; idx += NTHREADS) {
        int m = idx >> 6;
        int pp = idx & (TPAIR - 1);
        int a = m / NATOM;
        int b = m - a * NATOM;
        int ii = pp >> 3, jj = pp & 7;
        float dx = s.posI[ii * 42 + a * 3 + 0] - s.posJ[jj * 42 + b * 3 + 0];
        float dy = s.posI[ii * 42 + a * 3 + 1] - s.posJ[jj * 42 + b * 3 + 1];
        float dz = s.posI[ii * 42 + a * 3 + 2] - s.posJ[jj * 42 + b * 3 + 2];
        float ss = dx * dx + dy * dy + dz * dz;        // (10*d)^2
        float cc = g_softc[s.aap[pp] * MPAIR + m];
        float gv = __expf(-cc * ss * 0.01f) * (s.maskI[ii * NATOM + a] * s.maskJ[jj * NATOM + b]);
        s.bufG[idx] = gv;
    }
    // gemm's first __syncthreads covers bufG visibility

    ull acc[4][4];

    // ---- stage 1: h1 = relu(G @ dist_w1 + b1) -> bufB ----
    zero_acc(acc);
    gemm_db<MPAIR>(dw1, s.bufG, s.sW, acc, tid, lane, fbase);
    epilogue(acc, s.b1, s.bufB, lane, fbase);

    // ---- stage 2: fd = relu(h1 @ dist_w2 + b2) -> bufG rows 0..127 ----
    zero_acc(acc);
    gemm_db<FEAT>(dw2, s.bufB, s.sW, acc, tid, lane, fbase);
    epilogue(acc, s.b2, s.bufG, lane, fbase);
    // append dihedral codes as act rows 128..153 (visible by stage-3 gemm's first sync)
    for (int idx = tid; idx < 26 * TPAIR; idx += NTHREADS)
        s.bufG[FEAT * TPAIR + idx] = s.dcodeK[idx];

    // ---- stage 3: h = relu(preA + sc*preR + [fd;dihed] @ ow1[256:410] + ob1) -> bufB ----
    #pragma unroll
    for (int jp = 0; jp < 4; jp++) {
        int p0 = 8 * g + 2 * jp, p1 = p0 + 1;
        float sc0 = s.sc[p0], sc1 = s.sc[p1];
        float4 A0 = *(const float4*)&g_preA[s.aap[p0] * FEAT + fbase + 4 * q];
        float4 R0 = *(const float4*)&g_preR[s.rel[p0] * FEAT + fbase + 4 * q];
        float4 A1 = *(const float4*)&g_preA[s.aap[p1] * FEAT + fbase + 4 * q];
        float4 R1 = *(const float4*)&g_preR[s.rel[p1] * FEAT + fbase + 4 * q];
        acc[0][jp] = pack2(A0.x + sc0 * R0.x, A1.x + sc1 * R1.x);
        acc[1][jp] = pack2(A0.y + sc0 * R0.y, A1.y + sc1 * R1.y);
        acc[2][jp] = pack2(A0.z + sc0 * R0.z, A1.z + sc1 * R1.z);
        acc[3][jp] = pack2(A0.w + sc0 * R0.w, A1.w + sc1 * R1.w);
    }
    gemm_db<K3>(ow1 + 256 * FEAT, s.bufG, s.sW, acc, tid, lane, fbase);
    epilogue(acc, s.b3, s.bufB, lane, fbase);

    // ---- stage 4: h = relu(h @ out_w2 + ob2) -> bufG ----
    zero_acc(acc);
    gemm_db<FEAT>(ow2, s.bufB, s.sW, acc, tid, lane, fbase);
    epilogue(acc, s.b4, s.bufG, lane, fbase);

    // ---- stage 5: out = (h @ out_w3 + ob3) * mask_pair -> global ----
    zero_acc(acc);
    gemm_db<FEAT>(ow3, s.bufG, s.sW, acc, tid, lane, fbase);
    {
        int fofs = fbase + 4 * q;
        float b0 = s.b5[fofs], b1v = s.b5[fofs + 1], b2v = s.b5[fofs + 2], b3v = s.b5[fofs + 3];
        #pragma unroll
        for (int jp = 0; jp < 4; jp++) {
            float2 v0 = unpack2(acc[0][jp]);
            float2 v1 = unpack2(acc[1][jp]);
            float2 v2 = unpack2(acc[2][jp]);
            float2 v3 = unpack2(acc[3][jp]);
            int p0 = 8 * g + 2 * jp;
            int jj0 = p0 & 7;                  // ii == g always (p0 < 8g+8)
            float mp0 = s.mp[p0], mp1 = s.mp[p0 + 1];
            float* orow = outp + ((((size_t)n * LRES + (i0 + g)) * LRES + (j0 + jj0)) * FEAT + fofs);
            float4 o0 = make_float4((v0.x + b0) * mp0, (v1.x + b1v) * mp0,
                                    (v2.x + b2v) * mp0, (v3.x + b3v) * mp0);
            float4 o1 = make_float4((v0.y + b0) * mp1, (v1.y + b1v) * mp1,
                                    (v2.y + b2v) * mp1, (v3.y + b3v) * mp1);
            *(float4*)&orow[0]    = o0;
            *(float4*)&orow[FEAT] = o1;
        }
    }
}

// ---------------- launch ----------------
extern "C" void kernel_launch(void* const* d_in, const int* in_sizes, int n_in,
                              void* d_out, int out_size) {
    const int*   aa        = (const int*)  d_in[0];
    const int*   res_nb    = (const int*)  d_in[1];
    const int*   chain_nb  = (const int*)  d_in[2];
    const float* pos       = (const float*)d_in[3];
    const float* mask      = (const float*)d_in[4];
    const float* aap_embed = (const float*)d_in[5];
    const float* rel_embed = (const float*)d_in[6];
    const float* distcoef  = (const float*)d_in[7];
    const float* dw1 = (const float*)d_in[8];
    const float* db1 = (const float*)d_in[9];
    const float* dw2 = (const float*)d_in[10];
    const float* db2 = (const float*)d_in[11];
    const float* ow1 = (const float*)d_in[12];
    const float* ob1 = (const float*)d_in[13];
    const float* ow2 = (const float*)d_in[14];
    const float* ob2 = (const float*)d_in[15];
    const float* ow3 = (const float*)d_in[16];
    const float* ob3 = (const float*)d_in[17];
    float* outp = (float*)d_out;

    cudaFuncSetAttribute(fused_kernel, cudaFuncAttributeMaxDynamicSharedMemorySize,
                         (int)sizeof(Smem));

    softc_kernel<<<(NAPAIR * MPAIR + 255) / 256, 256>>>(distcoef);
    pretab_kernel<<<NAPAIR + NREL, 128>>>(aap_embed, rel_embed, ow1);
    dihed_kernel<<<(NBATCH * LRES * LRES) / 256, 256>>>(pos);
    fused_kernel<<<NBATCH * 32 * 32, NTHREADS, sizeof(Smem)>>>(
        aa, res_nb, chain_nb, pos, mask,
        dw1, db1, dw2, db2, ow1, ob1, ow2, ob2, ow3, ob3, outp);
}

// round 15
// speedup vs baseline: 1.1099x; 1.0450x over previous
#include <cuda_runtime.h>
#include <cstdint>

#define NBATCH 4
#define LRES   256
#define NATOM  14
#define FEAT   128
#define MPAIR  196      // NATOM*NATOM
#define MAXAA  22
#define NAPAIR 484      // MAXAA*MAXAA
#define NREL   65
#define TPAIR  64       // pairs per block tile (8 i-rows x 8 j-cols)
#define NTHREADS 256
#define K3     154      // stage-3 K: 128 dist + 26 dihedral (contiguous ow1 rows 256..409)

typedef unsigned long long ull;

// ---------------- scratch (static __device__ — no allocations allowed) ----------------
__device__ float g_softc[NAPAIR * MPAIR];          // softplus(distcoef_embed)
__device__ float g_preA [NAPAIR * FEAT];           // aa_pair_embed @ out_w1[0:128]
__device__ float g_preR [NREL   * FEAT];           // relpos_embed  @ out_w1[128:256]
__device__ float g_dihed[NBATCH * LRES * LRES * 2];// (phi, psi) per pair

// ---------------- packed f32x2 helpers ----------------
__device__ __forceinline__ ull pack2(float lo, float hi) {
    ull r; asm("mov.b64 %0, {%1, %2};" : "=l"(r) : "f"(lo), "f"(hi)); return r;
}
__device__ __forceinline__ void fma2(ull& d, ull a, ull b) {
    asm("fma.rn.f32x2 %0, %1, %2, %0;" : "+l"(d) : "l"(a), "l"(b));
}
__device__ __forceinline__ float2 unpack2(ull v) {
    float2 r; asm("mov.b64 {%0, %1}, %2;" : "=f"(r.x), "=f"(r.y) : "l"(v)); return r;
}

// ---------------- small precompute kernels ----------------
__global__ void softc_kernel(const float* __restrict__ distcoef) {
    int idx = blockIdx.x * 256 + threadIdx.x;
    if (idx < NAPAIR * MPAIR) {
        float x = distcoef[idx];
        g_softc[idx] = (x > 20.f) ? x : log1pf(expf(x));
    }
}

__global__ void pretab_kernel(const float* __restrict__ aa_pair_embed,
                              const float* __restrict__ relpos_embed,
                              const float* __restrict__ ow1) {
    __shared__ float e[FEAT];
    int b = blockIdx.x, f = threadIdx.x;
    if (b < NAPAIR) {
        e[f] = aa_pair_embed[b * FEAT + f];
        __syncthreads();
        float acc = 0.f;
        #pragma unroll 8
        for (int k = 0; k < FEAT; k++) acc += e[k] * ow1[k * FEAT + f];
        g_preA[b * FEAT + f] = acc;
    } else {
        int r = b - NAPAIR;
        e[f] = relpos_embed[r * FEAT + f];
        __syncthreads();
        float acc = 0.f;
        #pragma unroll 8
        for (int k = 0; k < FEAT; k++) acc += e[k] * ow1[(FEAT + k) * FEAT + f];
        g_preR[r * FEAT + f] = acc;
    }
}

__device__ __forceinline__ float3 f3sub(float3 a, float3 b) { return make_float3(a.x-b.x, a.y-b.y, a.z-b.z); }
__device__ __forceinline__ float3 f3cross(float3 a, float3 b) {
    return make_float3(a.y*b.z - a.z*b.y, a.z*b.x - a.x*b.z, a.x*b.y - a.y*b.x);
}
__device__ __forceinline__ float f3dot(float3 a, float3 b) { return a.x*b.x + a.y*b.y + a.z*b.z; }

__device__ __forceinline__ float dihedral_f(float3 p0, float3 p1, float3 p2, float3 p3) {
    float3 v0 = f3sub(p2, p1), v1 = f3sub(p0, p1), v2 = f3sub(p3, p2);
    float3 u1 = f3cross(v0, v1), u2 = f3cross(v0, v2);
    float nn = f3dot(u1, u1) * f3dot(u2, u2);
    if (!(nn > 0.f)) return 0.f;
    float cosv = f3dot(u1, u2) * rsqrtf(nn);
    cosv = fminf(fmaxf(cosv, -0.999999f), 0.999999f);
    float sd = f3dot(f3cross(v1, v2), v0);
    float sgn = (sd > 0.f) ? 1.f : ((sd < 0.f) ? -1.f : 0.f);
    float d = sgn * acosf(cosv);
    return isfinite(d) ? d : 0.f;
}

__global__ void dihed_kernel(const float* __restrict__ pos) {
    int idx = blockIdx.x * 256 + threadIdx.x;        // NB*L*L threads exactly
    int n = idx >> 16, i = (idx >> 8) & 255, j = idx & 255;
    const float* pi = pos + (size_t)(n * LRES + i) * NATOM * 3;
    const float* pj = pos + (size_t)(n * LRES + j) * NATOM * 3;
    float3 Ni  = make_float3(pi[0], pi[1], pi[2]);
    float3 CAi = make_float3(pi[3], pi[4], pi[5]);
    float3 Ci  = make_float3(pi[6], pi[7], pi[8]);
    float3 Nj  = make_float3(pj[0], pj[1], pj[2]);
    float3 CAj = make_float3(pj[3], pj[4], pj[5]);
    float3 Cj  = make_float3(pj[6], pj[7], pj[8]);
    float phi = dihedral_f(Ci, Nj, CAj, Cj);
    float psi = dihedral_f(Ni, CAi, Ci, Nj);
    g_dihed[(size_t)idx * 2 + 0] = phi;
    g_dihed[(size_t)idx * 2 + 1] = psi;
}

// ---------------- fused main kernel ----------------
// Tile: 64 pairs (8 i x 8 j) x 128 feat. 8 warps, 256 threads, 2 CTAs/SM.
// warp -> 16-feature slice [warp*16, warp*16+16). Within the warp:
//   q = lane&3  -> 4-feature sub-slice  f in [fbase+4q, fbase+4q+4)
//   g = lane>>2 -> pair octet           p in [8g, 8g+8)
// acc[fi][jp] (ull) = (out[8g+2jp][f], out[8g+2jp+1][f]), f = fbase+4q+fi.
// Weights are read DIRECTLY from global (L2-resident, coalesced 64B/warp/k-step)
// -> no smem staging, no per-chunk barriers; only one sync per stage boundary.
struct __align__(16) Smem {
    float bufG[MPAIR * TPAIR];  // 50.2KB: stage1 act; rows 0..153 = stage3 act
    float bufB[FEAT * TPAIR];   // 32KB ping-pong
    float dcodeK[26 * TPAIR];   // 6.7KB dihedral codes, k-major [t][p]
    float posI[8 * NATOM * 3];
    float posJ[8 * NATOM * 3];
    float maskI[8 * NATOM];
    float maskJ[8 * NATOM];
    float b1[FEAT]; float b2[FEAT]; float b3[FEAT]; float b4[FEAT]; float b5[FEAT];
    float sc[TPAIR]; float mp[TPAIR];
    int aap[TPAIR]; int rel[TPAIR];
    int aaI[8]; int aaJ[8]; int resI[8]; int resJ[8]; int chI[8]; int chJ[8];
};

// acc += sAct(k-major [k][64]) x W (global row-major [K][128]); no barriers inside.
template<int K>
__device__ __forceinline__ void gemm_direct(const float* __restrict__ Wg,
                                            const float* __restrict__ sAct,
                                            ull acc[4][4],
                                            int lane, int fbase) {
    const int q = lane & 3, g = lane >> 2;
    const float* wp = Wg + fbase + 4 * q;
    const float* ab = sAct + 8 * g;
    #pragma unroll 4
    for (int k = 0; k < K; k++) {
        float4 wv = __ldg((const float4*)(wp + k * FEAT));
        ulonglong2 au01 = *(const ulonglong2*)(ab + k * TPAIR);      // pairs 8g..8g+3
        ulonglong2 au23 = *(const ulonglong2*)(ab + k * TPAIR + 4);  // pairs 8g+4..8g+7
        ull w0 = pack2(wv.x, wv.x), w1 = pack2(wv.y, wv.y);
        ull w2 = pack2(wv.z, wv.z), w3 = pack2(wv.w, wv.w);
        fma2(acc[0][0], au01.x, w0); fma2(acc[0][1], au01.y, w0);
        fma2(acc[0][2], au23.x, w0); fma2(acc[0][3], au23.y, w0);
        fma2(acc[1][0], au01.x, w1); fma2(acc[1][1], au01.y, w1);
        fma2(acc[1][2], au23.x, w1); fma2(acc[1][3], au23.y, w1);
        fma2(acc[2][0], au01.x, w2); fma2(acc[2][1], au01.y, w2);
        fma2(acc[2][2], au23.x, w2); fma2(acc[2][3], au23.y, w2);
        fma2(acc[3][0], au01.x, w3); fma2(acc[3][1], au01.y, w3);
        fma2(acc[3][2], au23.x, w3); fma2(acc[3][3], au23.y, w3);
    }
}

// relu(acc + bias) -> dst in k-major layout dst[f][p] (16 STS.64, contiguous pairs)
__device__ __forceinline__ void epilogue(ull acc[4][4],
                                         const float* __restrict__ bias,
                                         float* __restrict__ dst, int lane, int fbase) {
    const int q = lane & 3, g = lane >> 2;
    #pragma unroll
    for (int fi = 0; fi < 4; fi++) {
        int f = fbase + 4 * q + fi;
        float bf = bias[f];
        #pragma unroll
        for (int jp = 0; jp < 4; jp++) {
            float2 v = unpack2(acc[fi][jp]);
            float2 o = make_float2(fmaxf(v.x + bf, 0.f), fmaxf(v.y + bf, 0.f));
            *(float2*)&dst[f * TPAIR + 8 * g + 2 * jp] = o;
        }
    }
}

__device__ __forceinline__ void zero_acc(ull acc[4][4]) {
    #pragma unroll
    for (int a = 0; a < 4; a++)
        #pragma unroll
        for (int b = 0; b < 4; b++) acc[a][b] = 0ull;
}

__global__ void __launch_bounds__(NTHREADS, 2)
fused_kernel(const int* __restrict__ aa, const int* __restrict__ res_nb,
             const int* __restrict__ chain_nb, const float* __restrict__ pos,
             const float* __restrict__ mask,
             const float* __restrict__ dw1, const float* __restrict__ db1,
             const float* __restrict__ dw2, const float* __restrict__ db2,
             const float* __restrict__ ow1, const float* __restrict__ ob1,
             const float* __restrict__ ow2, const float* __restrict__ ob2,
             const float* __restrict__ ow3, const float* __restrict__ ob3,
             float* __restrict__ outp) {
    extern __shared__ char smem_raw[];
    Smem& s = *reinterpret_cast<Smem*>(smem_raw);
    const int tid = threadIdx.x;
    const int warp = tid >> 5, lane = tid & 31;
    const int fbase = warp * 16;
    const int q = lane & 3, g = lane >> 2;
    const int bid = blockIdx.x;
    const int n  = bid >> 10;                // 32*32 tiles per batch
    const int i0 = ((bid >> 5) & 31) * 8;
    const int j0 = (bid & 31) * 8;

    // ---- phase 0: cooperative loads ----
    {
        const float* pbI = pos + (size_t)(n * LRES + i0) * NATOM * 3;
        const float* pbJ = pos + (size_t)(n * LRES + j0) * NATOM * 3;
        for (int idx = tid; idx < 8 * NATOM * 3; idx += NTHREADS) { s.posI[idx] = pbI[idx]; s.posJ[idx] = pbJ[idx]; }
        const float* mbI = mask + (size_t)(n * LRES + i0) * NATOM;
        const float* mbJ = mask + (size_t)(n * LRES + j0) * NATOM;
        if (tid < 8 * NATOM) { s.maskI[tid] = mbI[tid]; s.maskJ[tid] = mbJ[tid]; }
        if (tid < 8) {
            s.aaI[tid]  = aa[n * LRES + i0 + tid];
            s.resI[tid] = res_nb[n * LRES + i0 + tid];
            s.chI[tid]  = chain_nb[n * LRES + i0 + tid];
        }
        if (tid >= 32 && tid < 40) {
            int t = tid - 32;
            s.aaJ[t]  = aa[n * LRES + j0 + t];
            s.resJ[t] = res_nb[n * LRES + j0 + t];
            s.chJ[t]  = chain_nb[n * LRES + j0 + t];
        }
        if (tid >= 64 && tid < 192) {
            int t = tid - 64;
            s.b1[t] = db1[t]; s.b2[t] = db2[t]; s.b3[t] = ob1[t];
            s.b4[t] = ob2[t]; s.b5[t] = ob3[t];
        }
    }
    __syncthreads();

    // ---- phase 0b: per-pair meta + dihedral angular codes (k-major) ----
    if (tid < TPAIR) {
        int ii = tid >> 3, jj = tid & 7;
        s.aap[tid] = s.aaI[ii] * MAXAA + s.aaJ[jj];
        int r = s.resI[ii] - s.resJ[jj];
        s.rel[tid] = min(max(r, -32), 32) + 32;
        s.sc[tid] = (s.chI[ii] == s.chJ[jj]) ? 1.f : 0.f;
        s.mp[tid] = s.maskI[ii * NATOM + 1] * s.maskJ[jj * NATOM + 1];   // CA masks
        const float* dh = &g_dihed[((size_t)(n * LRES + i0 + ii) * LRES + (j0 + jj)) * 2];
        float phi = dh[0], psi = dh[1];
        const float FRQ[6] = {1.f, 2.f, 3.f, 1.f, 0.5f, 1.f / 3.f};
        s.dcodeK[0 * TPAIR + tid]  = phi;
        s.dcodeK[13 * TPAIR + tid] = psi;
        #pragma unroll
        for (int t = 0; t < 6; t++) {
            float sv, cv;
            sincosf(phi * FRQ[t], &sv, &cv);
            s.dcodeK[(1 + t) * TPAIR + tid]  = sv;
            s.dcodeK[(7 + t) * TPAIR + tid]  = cv;
            sincosf(psi * FRQ[t], &sv, &cv);
            s.dcodeK[(14 + t) * TPAIR + tid] = sv;
            s.dcodeK[(20 + t) * TPAIR + tid] = cv;
        }
    }
    __syncthreads();

    // ---- phase 1: masked gaussian distance features, k-major G[m][p] ----
    for (int idx = tid; idx < TPAIR * MPAIR; idx += NTHREADS) {
        int m = idx >> 6;
        int pp = idx & (TPAIR - 1);
        int a = m / NATOM;
        int b = m - a * NATOM;
        int ii = pp >> 3, jj = pp & 7;
        float dx = s.posI[ii * 42 + a * 3 + 0] - s.posJ[jj * 42 + b * 3 + 0];
        float dy = s.posI[ii * 42 + a * 3 + 1] - s.posJ[jj * 42 + b * 3 + 1];
        float dz = s.posI[ii * 42 + a * 3 + 2] - s.posJ[jj * 42 + b * 3 + 2];
        float ss = dx * dx + dy * dy + dz * dz;        // (10*d)^2
        float cc = g_softc[s.aap[pp] * MPAIR + m];
        float gv = __expf(-cc * ss * 0.01f) * (s.maskI[ii * NATOM + a] * s.maskJ[jj * NATOM + b]);
        s.bufG[idx] = gv;
    }
    __syncthreads();   // bufG ready for stage 1

    ull acc[4][4];

    // ---- stage 1: h1 = relu(G @ dist_w1 + b1) -> bufB ----
    zero_acc(acc);
    gemm_direct<MPAIR>(dw1, s.bufG, acc, lane, fbase);
    epilogue(acc, s.b1, s.bufB, lane, fbase);
    __syncthreads();

    // ---- stage 2: fd = relu(h1 @ dist_w2 + b2) -> bufG rows 0..127 ----
    zero_acc(acc);
    gemm_direct<FEAT>(dw2, s.bufB, acc, lane, fbase);
    epilogue(acc, s.b2, s.bufG, lane, fbase);
    // append dihedral codes as act rows 128..153
    for (int idx = tid; idx < 26 * TPAIR; idx += NTHREADS)
        s.bufG[FEAT * TPAIR + idx] = s.dcodeK[idx];
    __syncthreads();

    // ---- stage 3: h = relu(preA + sc*preR + [fd;dihed] @ ow1[256:410] + ob1) -> bufB ----
    #pragma unroll
    for (int jp = 0; jp < 4; jp++) {
        int p0 = 8 * g + 2 * jp, p1 = p0 + 1;
        float sc0 = s.sc[p0], sc1 = s.sc[p1];
        float4 A0 = *(const float4*)&g_preA[s.aap[p0] * FEAT + fbase + 4 * q];
        float4 R0 = *(const float4*)&g_preR[s.rel[p0] * FEAT + fbase + 4 * q];
        float4 A1 = *(const float4*)&g_preA[s.aap[p1] * FEAT + fbase + 4 * q];
        float4 R1 = *(const float4*)&g_preR[s.rel[p1] * FEAT + fbase + 4 * q];
        acc[0][jp] = pack2(A0.x + sc0 * R0.x, A1.x + sc1 * R1.x);
        acc[1][jp] = pack2(A0.y + sc0 * R0.y, A1.y + sc1 * R1.y);
        acc[2][jp] = pack2(A0.z + sc0 * R0.z, A1.z + sc1 * R1.z);
        acc[3][jp] = pack2(A0.w + sc0 * R0.w, A1.w + sc1 * R1.w);
    }
    gemm_direct<K3>(ow1 + 256 * FEAT, s.bufG, acc, lane, fbase);
    epilogue(acc, s.b3, s.bufB, lane, fbase);
    __syncthreads();

    // ---- stage 4: h = relu(h @ out_w2 + ob2) -> bufG ----
    zero_acc(acc);
    gemm_direct<FEAT>(ow2, s.bufB, acc, lane, fbase);
    epilogue(acc, s.b4, s.bufG, lane, fbase);
    __syncthreads();

    // ---- stage 5: out = (h @ out_w3 + ob3) * mask_pair -> global ----
    zero_acc(acc);
    gemm_direct<FEAT>(ow3, s.bufG, acc, lane, fbase);
    {
        int fofs = fbase + 4 * q;
        float b0 = s.b5[fofs], b1v = s.b5[fofs + 1], b2v = s.b5[fofs + 2], b3v = s.b5[fofs + 3];
        #pragma unroll
        for (int jp = 0; jp < 4; jp++) {
            float2 v0 = unpack2(acc[0][jp]);
            float2 v1 = unpack2(acc[1][jp]);
            float2 v2 = unpack2(acc[2][jp]);
            float2 v3 = unpack2(acc[3][jp]);
            int p0 = 8 * g + 2 * jp;
            int jj0 = p0 & 7;                  // ii == g always (p0 < 8g+8)
            float mp0 = s.mp[p0], mp1 = s.mp[p0 + 1];
            float* orow = outp + ((((size_t)n * LRES + (i0 + g)) * LRES + (j0 + jj0)) * FEAT + fofs);
            float4 o0 = make_float4((v0.x + b0) * mp0, (v1.x + b1v) * mp0,
                                    (v2.x + b2v) * mp0, (v3.x + b3v) * mp0);
            float4 o1 = make_float4((v0.y + b0) * mp1, (v1.y + b1v) * mp1,
                                    (v2.y + b2v) * mp1, (v3.y + b3v) * mp1);
            *(float4*)&orow[0]    = o0;
            *(float4*)&orow[FEAT] = o1;
        }
    }
}

// ---------------- launch ----------------
extern "C" void kernel_launch(void* const* d_in, const int* in_sizes, int n_in,
                              void* d_out, int out_size) {
    const int*   aa        = (const int*)  d_in[0];
    const int*   res_nb    = (const int*)  d_in[1];
    const int*   chain_nb  = (const int*)  d_in[2];
    const float* pos       = (const float*)d_in[3];
    const float* mask      = (const float*)d_in[4];
    const float* aap_embed = (const float*)d_in[5];
    const float* rel_embed = (const float*)d_in[6];
    const float* distcoef  = (const float*)d_in[7];
    const float* dw1 = (const float*)d_in[8];
    const float* db1 = (const float*)d_in[9];
    const float* dw2 = (const float*)d_in[10];
    const float* db2 = (const float*)d_in[11];
    const float* ow1 = (const float*)d_in[12];
    const float* ob1 = (const float*)d_in[13];
    const float* ow2 = (const float*)d_in[14];
    const float* ob2 = (const float*)d_in[15];
    const float* ow3 = (const float*)d_in[16];
    const float* ob3 = (const float*)d_in[17];
    float* outp = (float*)d_out;

    cudaFuncSetAttribute(fused_kernel, cudaFuncAttributeMaxDynamicSharedMemorySize,
                         (int)sizeof(Smem));

    softc_kernel<<<(NAPAIR * MPAIR + 255) / 256, 256>>>(distcoef);
    pretab_kernel<<<NAPAIR + NREL, 128>>>(aap_embed, rel_embed, ow1);
    dihed_kernel<<<(NBATCH * LRES * LRES) / 256, 256>>>(pos);
    fused_kernel<<<NBATCH * 32 * 32, NTHREADS, sizeof(Smem)>>>(
        aa, res_nb, chain_nb, pos, mask,
        dw1, db1, dw2, db2, ow1, ob1, ow2, ob2, ow3, ob3, outp);
}